// round 2
// baseline (speedup 1.0000x reference)
#include <cuda_runtime.h>
#include <cstdint>

#define VM_D       16
#define VM_HALF    8
#define VM_NINC    1000
#define VM_BLOCK   512
#define VM_NPAIR   148           // sample-chunk pairs == SM count on sm_100a
#define VM_CTAS    (VM_NPAIR*2)  // 296 CTAs, 2 per SM (one wave)
#define VM_BMAX    (1u << 20)

// smem: float2 pairs[8*1000] = (grid[d][i], inc[d][i]) for this CTA's 8 dims,
// then float edge[8] = grid[d][NINC]
#define VM_SMEM_BYTES (VM_HALF * VM_NINC * sizeof(float2) + VM_HALF * sizeof(float))

__device__ float g_jacA[VM_BMAX];
__device__ float g_jacB[VM_BMAX];

__global__ __launch_bounds__(VM_BLOCK, 2)
void vegas_map_half_kernel(const float* __restrict__ y,
                           const float* __restrict__ grid,
                           const float* __restrict__ inc,
                           float* __restrict__ x_out,
                           int B)
{
    extern __shared__ unsigned char smem_raw[];
    float2* __restrict__ pairs = reinterpret_cast<float2*>(smem_raw);
    float*  __restrict__ edge  = reinterpret_cast<float*>(smem_raw + VM_HALF * VM_NINC * sizeof(float2));

    const int tid   = threadIdx.x;
    const int ctype = blockIdx.x & 1;        // 0: dims 0-7, 1: dims 8-15
    const int cid   = blockIdx.x >> 1;       // sample-chunk id (shared by the pair)

    // ---- Fill this half's interleaved (grid, inc) table ----
    const int dg0 = ctype * VM_HALF;
    #pragma unroll
    for (int d = 0; d < VM_HALF; ++d) {
        const float* grow = grid + (dg0 + d) * (VM_NINC + 1);
        const float* irow = inc  + (dg0 + d) * VM_NINC;
        for (int i = tid; i < VM_NINC; i += VM_BLOCK) {
            pairs[d * VM_NINC + i] = make_float2(__ldg(grow + i), __ldg(irow + i));
        }
    }
    if (tid < VM_HALF) {
        edge[tid] = __ldg(grid + (dg0 + tid) * (VM_NINC + 1) + VM_NINC);
    }
    __syncthreads();

    // Thread handles one float4 (4 dims) of its half-row; pair (q=0,1) covers the half.
    const int q   = tid & 1;                 // which float4 within the half
    const int sth = tid >> 1;                // sample slot within CTA (0..255)
    const float2* __restrict__ pb = pairs + q * 4 * VM_NINC;
    const float e0 = edge[q * 4 + 0];
    const float e1 = edge[q * 4 + 1];
    const float e2 = edge[q * 4 + 2];
    const float e3 = edge[q * 4 + 3];

    const float4* __restrict__ y4 = reinterpret_cast<const float4*>(y);
    float4* __restrict__       x4 = reinterpret_cast<float4*>(x_out);
    float* __restrict__ jac_part  = ctype ? g_jacB : g_jacA;

    const float ninc_f = (float)VM_NINC;

    const int spp    = (B + VM_NPAIR - 1) / VM_NPAIR;     // samples per chunk
    const int sstart = cid * spp;
    const int send   = min(sstart + spp, B);

    #pragma unroll 4
    for (int s = sstart + sth; s < send; s += (VM_BLOCK / 2)) {
        const int f4 = s * 4 + ctype * 2 + q;
        const float4 yv = __ldg(y4 + f4);

        float4 xv;
        float fac;

        {
            float t = yv.x * ninc_f;
            int   iy = __float2int_rd(t);
            bool  valid = (t < ninc_f);
            int   iyc = valid ? iy : (VM_NINC - 1);
            float2 p = pb[iyc];
            xv.x = valid ? fmaf(p.y, t - (float)iy, p.x) : e0;
            fac  = p.y * ninc_f;
        }
        {
            float t = yv.y * ninc_f;
            int   iy = __float2int_rd(t);
            bool  valid = (t < ninc_f);
            int   iyc = valid ? iy : (VM_NINC - 1);
            float2 p = pb[VM_NINC + iyc];
            xv.y = valid ? fmaf(p.y, t - (float)iy, p.x) : e1;
            fac *= p.y * ninc_f;
        }
        {
            float t = yv.z * ninc_f;
            int   iy = __float2int_rd(t);
            bool  valid = (t < ninc_f);
            int   iyc = valid ? iy : (VM_NINC - 1);
            float2 p = pb[2 * VM_NINC + iyc];
            xv.z = valid ? fmaf(p.y, t - (float)iy, p.x) : e2;
            fac *= p.y * ninc_f;
        }
        {
            float t = yv.w * ninc_f;
            int   iy = __float2int_rd(t);
            bool  valid = (t < ninc_f);
            int   iyc = valid ? iy : (VM_NINC - 1);
            float2 p = pb[3 * VM_NINC + iyc];
            xv.w = valid ? fmaf(p.y, t - (float)iy, p.x) : e3;
            fac *= p.y * ninc_f;
        }

        x4[f4] = xv;

        // combine the two quads of this half (lanes 2k / 2k+1)
        fac *= __shfl_xor_sync(0xFFFFFFFFu, fac, 1);
        if (q == 0) {
            jac_part[s] = fac;
        }
    }
}

__global__ __launch_bounds__(256)
void vegas_jac_combine_kernel(float* __restrict__ jac_out, int n4)
{
    const float4* __restrict__ a4 = reinterpret_cast<const float4*>(g_jacA);
    const float4* __restrict__ b4 = reinterpret_cast<const float4*>(g_jacB);
    float4* __restrict__ o4 = reinterpret_cast<float4*>(jac_out);

    for (int i = blockIdx.x * 256 + threadIdx.x; i < n4; i += gridDim.x * 256) {
        float4 a = a4[i];
        float4 b = b4[i];
        float4 o;
        o.x = a.x * b.x;
        o.y = a.y * b.y;
        o.z = a.z * b.z;
        o.w = a.w * b.w;
        o4[i] = o;
    }
}

extern "C" void kernel_launch(void* const* d_in, const int* in_sizes, int n_in,
                              void* d_out, int out_size)
{
    const float* y    = (const float*)d_in[0];
    const float* grid = (const float*)d_in[1];
    const float* inc  = (const float*)d_in[2];

    const int B = in_sizes[0] / VM_D;               // 1,048,576
    float* x   = (float*)d_out;                     // [B,16]
    float* jac = (float*)d_out + (size_t)B * VM_D;  // [B]

    static int smem_set = 0;
    cudaFuncSetAttribute(vegas_map_half_kernel,
                         cudaFuncAttributeMaxDynamicSharedMemorySize,
                         (int)VM_SMEM_BYTES);
    (void)smem_set;

    vegas_map_half_kernel<<<VM_CTAS, VM_BLOCK, VM_SMEM_BYTES>>>(y, grid, inc, x, B);

    const int n4 = B / 4;
    vegas_jac_combine_kernel<<<512, 256>>>(jac, n4);
}